// round 11
// baseline (speedup 1.0000x reference)
#include <cuda_runtime.h>

#define N_NODES   100000
#define N_EDGES   1600000
#define HIDDEN    64
#define EMB       2
#define N_GRAPHS  64

#define EDGE_GRID 1184   // 148 SMs x 8 CTAs (fits 152-SM GB300 too: <=1216)
#define TB        256
#define N_CHUNK4  (N_EDGES / 4)     // 400000 4-edge chunks (E % 4 == 0)
#define SG_GRID   256               // stats+gnode fused grid (needs only 2 CTAs/SM)

// ---------------- scratch (device globals; zero-initialized at load) -------------
// INVARIANT: every kernel_launch call leaves all accumulators/counters zeroed for
// the next replay (self-cleaning in the last ticket block of k_l2pool).
__device__ float  d_dinv[N_NODES];          // Σw in-degree (no self), then rsqrt(deg+1)
__device__ float  d_xd[N_NODES];            // dinv[n] * x[n]
__device__ float  d_p[N_NODES];             // layer-1 unnormalized sum
__device__ float2 d_gd[N_NODES];            // dinv[n] * g[n]
__device__ float2 d_u[N_NODES];             // layer-2 unnormalized aggregate
__device__ float  d_sums[2];                // sum(p), sum(p^2)
__device__ float  d_acc[N_GRAPHS * EMB];    // pooled sums
__device__ float  d_cnt[N_GRAPHS];          // nodes per graph
__device__ unsigned d_bar_deg;              // grid barrier counter (deg+dinv)
__device__ unsigned d_bar_sg;               // grid barrier counter (stats+gnode)
__device__ unsigned d_bar_l2;               // grid barrier counter (l2+pool)
__device__ unsigned d_ticket;               // last-block ticket (pool finalize)

// Vector reduction: one RED.E.ADD.F32x2 per edge (PTX ISA 8.1+, sm_90+)
__device__ __forceinline__ void red_add_f32x2(float2* addr, float a, float b) {
    asm volatile("red.global.add.v2.f32 [%0], {%1, %2};"
                 :: "l"(addr), "f"(a), "f"(b) : "memory");
}

// Grid barrier: every block arrives (tid 0), spins until all `expect` arrived.
// Caller must guarantee all blocks are co-resident.
__device__ __forceinline__ void grid_barrier(unsigned* ctr, unsigned expect) {
    __syncthreads();
    if (threadIdx.x == 0) {
        __threadfence();
        atomicAdd(ctr, 1u);
        while (*((volatile unsigned*)ctr) < expect) { }
    }
    __syncthreads();
    __threadfence();
}

// ---------------- kernels ----------------

// Fused: Phase A weighted in-degree (deg[d] += w[e]); barrier;
//        Phase B dinv = rsqrt(deg+1), xd = dinv*x, seed p with xd (self term).
// __launch_bounds__(TB, 8): regs capped at 32 -> 8 CTAs/SM -> all 1184 resident.
__global__ void __launch_bounds__(TB, 8)
k_degdinv(const int* __restrict__ dst, const float* __restrict__ w,
          const float* __restrict__ x) {
    const int stride = EDGE_GRID * TB;
    for (int c = blockIdx.x * TB + threadIdx.x; c < N_CHUNK4; c += stride) {
        int e = c * 4;
        int4   d4 = __ldcs((const int4*)  (dst + e));
        float4 w4 = __ldcs((const float4*)(w   + e));
        atomicAdd(&d_dinv[d4.x], w4.x);
        atomicAdd(&d_dinv[d4.y], w4.y);
        atomicAdd(&d_dinv[d4.z], w4.z);
        atomicAdd(&d_dinv[d4.w], w4.w);
    }
    grid_barrier(&d_bar_deg, EDGE_GRID);
    for (int n = blockIdx.x * TB + threadIdx.x; n < N_NODES; n += stride) {
        float di = rsqrtf(__ldcv(&d_dinv[n]) + 1.0f);
        float xd = di * x[n];
        d_dinv[n] = di;
        d_xd[n] = xd;
        d_p[n] = xd;                // self-loop seed (unnormalized)
    }
}

// Pass 2: p'[d] += w * xd[s].  Single 4B gather per edge; grid-stride chunks.
__global__ void __launch_bounds__(TB)
k_p_edges(const int* __restrict__ src, const int* __restrict__ dst,
          const float* __restrict__ w) {
    const int stride = EDGE_GRID * TB;
    for (int c = blockIdx.x * TB + threadIdx.x; c < N_CHUNK4; c += stride) {
        int e = c * 4;
        int4   s4 = __ldcs((const int4*)  (src + e));
        int4   d4 = __ldcs((const int4*)  (dst + e));
        float4 w4 = __ldcs((const float4*)(w   + e));
        float x0 = __ldg(d_xd + s4.x), x1 = __ldg(d_xd + s4.y);
        float x2 = __ldg(d_xd + s4.z), x3 = __ldg(d_xd + s4.w);
        atomicAdd(&d_p[d4.x], w4.x * x0);
        atomicAdd(&d_p[d4.y], w4.y * x1);
        atomicAdd(&d_p[d4.z], w4.z * x2);
        atomicAdd(&d_p[d4.w], w4.w * x3);
    }
}

// Fused stats + gnode with in-kernel grid barrier. Each thread keeps its p
// values in registers across the barrier.
//   Phase A: p = dinv*p', accumulate sum(p), sum(p^2) to d_sums, arrive.
//   Phase B: BN coefs from d_sums (b1 cancels); g = relu(a*q+beta)@W2;
//            gd = dinv*g; u seeded with gd (self term).
#define SG_NPT ((N_NODES + SG_GRID * TB - 1) / (SG_GRID * TB))   // nodes/thread (2)
__global__ void __launch_bounds__(TB)
k_statsgnode(const float* __restrict__ W1, const float* __restrict__ gamma,
             const float* __restrict__ beta, const float* __restrict__ W2) {
    int tid = threadIdx.x;
    int base = blockIdx.x * TB + tid;
    const int stride = SG_GRID * TB;

    // Phase A
    float pv[SG_NPT];
    float v = 0.0f, v2 = 0.0f;
    #pragma unroll
    for (int i = 0; i < SG_NPT; i++) {
        int n = base + i * stride;
        float t = 0.0f;
        if (n < N_NODES) t = d_dinv[n] * d_p[n];
        pv[i] = t;
        v += t; v2 += t * t;
    }
    #pragma unroll
    for (int off = 16; off > 0; off >>= 1) {
        v  += __shfl_down_sync(0xffffffffu, v,  off);
        v2 += __shfl_down_sync(0xffffffffu, v2, off);
    }
    __shared__ float s1[8], s2[8];
    int lane = tid & 31, warp = tid >> 5;
    if (lane == 0) { s1[warp] = v; s2[warp] = v2; }
    __syncthreads();
    if (warp == 0) {
        v  = (lane < 8) ? s1[lane] : 0.0f;
        v2 = (lane < 8) ? s2[lane] : 0.0f;
        #pragma unroll
        for (int off = 4; off > 0; off >>= 1) {
            v  += __shfl_down_sync(0xffffffffu, v,  off);
            v2 += __shfl_down_sync(0xffffffffu, v2, off);
        }
        if (lane == 0) { atomicAdd(&d_sums[0], v); atomicAdd(&d_sums[1], v2); }
    }
    grid_barrier(&d_bar_sg, SG_GRID);

    // Phase B
    float mp   = __ldcv(&d_sums[0]) * (1.0f / N_NODES);
    float sp2  = __ldcv(&d_sums[1]) * (1.0f / N_NODES);
    float varp = sp2 - mp * mp;
    __shared__ float sa[HIDDEN], sb[HIDDEN], sw[HIDDEN * EMB];
    if (tid < HIDDEN) {
        float wj = W1[tid];
        sa[tid] = wj * gamma[tid] * rsqrtf(wj * wj * varp + 1e-5f);
        sb[tid] = beta[tid];
    }
    if (tid < HIDDEN * EMB) sw[tid] = W2[tid];
    __syncthreads();
    #pragma unroll
    for (int i = 0; i < SG_NPT; i++) {
        int n = base + i * stride;
        if (n >= N_NODES) continue;
        float q = pv[i] - mp;
        float g0 = 0.0f, g1 = 0.0f;
        #pragma unroll
        for (int j = 0; j < HIDDEN; j++) {
            float r = fmaxf(sa[j] * q + sb[j], 0.0f);
            g0 = fmaf(r, sw[j * EMB + 0], g0);
            g1 = fmaf(r, sw[j * EMB + 1], g1);
        }
        float di = d_dinv[n];
        float2 gd = make_float2(di * g0, di * g1);
        d_gd[n] = gd;
        d_u[n] = gd;                // self-loop seed (unnormalized)
    }
}

// Fused: Phase A layer-2 edges (u[d] += w*gd[s], f32x2 RED); barrier;
//        Phase B pool (t = dinv*u, smem pre-agg, global atomics); ticket;
//        last block finalizes out and resets ALL persistent state.
__global__ void __launch_bounds__(TB, 8)
k_l2pool(const int* __restrict__ src, const int* __restrict__ dst,
         const float* __restrict__ w, const int* __restrict__ batch,
         const float* __restrict__ b2, float* __restrict__ out) {
    const int stride = EDGE_GRID * TB;
    int tid = threadIdx.x;

    // Phase A: edges
    for (int c = blockIdx.x * TB + tid; c < N_CHUNK4; c += stride) {
        int e = c * 4;
        int4   s4 = __ldcs((const int4*)  (src + e));
        int4   d4 = __ldcs((const int4*)  (dst + e));
        float4 w4 = __ldcs((const float4*)(w   + e));
        float2 g0 = d_gd[s4.x], g1 = d_gd[s4.y], g2 = d_gd[s4.z], g3 = d_gd[s4.w];
        red_add_f32x2(&d_u[d4.x], w4.x * g0.x, w4.x * g0.y);
        red_add_f32x2(&d_u[d4.y], w4.y * g1.x, w4.y * g1.y);
        red_add_f32x2(&d_u[d4.z], w4.z * g2.x, w4.z * g2.y);
        red_add_f32x2(&d_u[d4.w], w4.w * g3.x, w4.w * g3.y);
    }
    grid_barrier(&d_bar_l2, EDGE_GRID);

    // Phase B: pool (grid-stride over nodes; smem pre-aggregation)
    __shared__ float sacc[N_GRAPHS * EMB];
    __shared__ float scnt[N_GRAPHS];
    __shared__ bool  is_last;
    if (tid < N_GRAPHS * EMB) sacc[tid] = 0.0f;
    if (tid < N_GRAPHS) scnt[tid] = 0.0f;
    __syncthreads();
    for (int n = blockIdx.x * TB + tid; n < N_NODES; n += stride) {
        int b = batch[n];
        float di = d_dinv[n];
        float2 u = __ldcv(&d_u[n]);   // .cv load: L2-coherent view of RED results
        atomicAdd(&sacc[b * EMB + 0], di * u.x);
        atomicAdd(&sacc[b * EMB + 1], di * u.y);
        atomicAdd(&scnt[b], 1.0f);
        d_dinv[n] = 0.0f;           // reset for next replay (after last use)
    }
    __syncthreads();
    if (tid < N_GRAPHS * EMB) atomicAdd(&d_acc[tid], sacc[tid]);
    if (tid < N_GRAPHS) atomicAdd(&d_cnt[tid], scnt[tid]);
    __threadfence();
    if (tid == 0) {
        unsigned old = atomicInc(&d_ticket, 0xffffffffu);
        is_last = (old == EDGE_GRID - 1);
    }
    __syncthreads();
    if (is_last) {
        if (tid < N_GRAPHS * EMB) {
            int g = tid / EMB, k = tid % EMB;
            float acc = __ldcv(&d_acc[tid]);
            float cnt = __ldcv(&d_cnt[g]);
            out[tid] = acc / fmaxf(cnt, 1.0f) + b2[k];
        }
        __syncthreads();
        // reset ALL persistent accumulators/counters for next replay.
        // Safe: every other block has exited its barrier spin (it took a ticket),
        // and all earlier kernels are separated by kernel boundaries.
        if (tid < N_GRAPHS * EMB) d_acc[tid] = 0.0f;
        if (tid < N_GRAPHS) d_cnt[tid] = 0.0f;
        if (tid == 0) {
            d_sums[0] = 0.0f; d_sums[1] = 0.0f;
            d_bar_deg = 0u; d_bar_sg = 0u; d_bar_l2 = 0u; d_ticket = 0u;
        }
    }
}

// ---------------- launch ----------------
extern "C" void kernel_launch(void* const* d_in, const int* in_sizes, int n_in,
                              void* d_out, int out_size) {
    const float* x     = (const float*)d_in[0];
    const int*   ei    = (const int*)  d_in[1];   // [2, E]: src row then dst row
    const float* ew    = (const float*)d_in[2];
    const int*   batch = (const int*)  d_in[3];
    const float* W1    = (const float*)d_in[4];
    // d_in[5] = b1 (cancels exactly inside batch-norm; unused)
    const float* gamma = (const float*)d_in[6];
    const float* beta  = (const float*)d_in[7];
    const float* W2    = (const float*)d_in[8];
    const float* b2    = (const float*)d_in[9];
    float* out = (float*)d_out;

    const int* src = ei;
    const int* dst = ei + N_EDGES;

    k_degdinv   <<<EDGE_GRID, TB>>>(dst, ew, x);
    k_p_edges   <<<EDGE_GRID, TB>>>(src, dst, ew);
    k_statsgnode<<<SG_GRID, TB>>>(W1, gamma, beta, W2);
    k_l2pool    <<<EDGE_GRID, TB>>>(src, dst, ew, batch, b2, out);
}

// round 12
// speedup vs baseline: 1.2553x; 1.2553x over previous
#include <cuda_runtime.h>

#define N_NODES   100000
#define N_EDGES   1600000
#define HIDDEN    64
#define EMB       2
#define N_GRAPHS  64

#define EDGE_GRID 1184   // 148 SMs x 8 CTAs of 256 threads = one full wave
#define TB        256
#define N_CHUNK4  (N_EDGES / 4)     // 400000 4-edge chunks (E % 4 == 0)
#define SG_GRID   256               // stats+gnode fused grid (needs only 2 CTAs/SM)

// ---------------- scratch (device globals; zero-initialized at load) -------------
// INVARIANT: every kernel_launch call leaves all accumulators/counters zeroed for
// the next replay (self-cleaning in k_pool's last ticket block).
__device__ float  d_dinv[N_NODES];          // Σw in-degree (no self), then rsqrt(deg+1)
__device__ float  d_xd[N_NODES];            // dinv[n] * x[n]
__device__ float  d_p[N_NODES];             // layer-1 unnormalized sum
__device__ float2 d_gd[N_NODES];            // dinv[n] * g[n]
__device__ float2 d_u[N_NODES];             // layer-2 unnormalized aggregate
__device__ float  d_sums[2];                // sum(p), sum(p^2)
__device__ float  d_acc[N_GRAPHS * EMB];    // pooled sums
__device__ float  d_cnt[N_GRAPHS];          // nodes per graph
__device__ unsigned d_bar_sg;               // grid barrier counter (stats+gnode only)
__device__ unsigned d_ticket;               // last-block ticket (pool finalize)

// Vector reduction: one RED.E.ADD.F32x2 per edge (PTX ISA 8.1+, sm_90+)
__device__ __forceinline__ void red_add_f32x2(float2* addr, float a, float b) {
    asm volatile("red.global.add.v2.f32 [%0], {%1, %2};"
                 :: "l"(addr), "f"(a), "f"(b) : "memory");
}

// ---------------- kernels ----------------

// Pass 1: weighted in-degree  deg[d] += w[e].  Grid-stride over 4-edge chunks.
__global__ void __launch_bounds__(TB)
k_deg(const int* __restrict__ dst, const float* __restrict__ w) {
    const int stride = EDGE_GRID * TB;
    for (int c = blockIdx.x * TB + threadIdx.x; c < N_CHUNK4; c += stride) {
        int e = c * 4;
        int4   d4 = __ldcs((const int4*)  (dst + e));
        float4 w4 = __ldcs((const float4*)(w   + e));
        atomicAdd(&d_dinv[d4.x], w4.x);
        atomicAdd(&d_dinv[d4.y], w4.y);
        atomicAdd(&d_dinv[d4.z], w4.z);
        atomicAdd(&d_dinv[d4.w], w4.w);
    }
}

// dinv = rsqrt(deg+1) (self-loop folded); xd = dinv*x; seed p with xd (self term).
// (p_final[d] = dinv[d] * [ Σ_s w*xd[s] + xd[d] ] — dinv[d] applied in stats phase)
__global__ void k_dinv(const float* __restrict__ x) {
    int n = blockIdx.x * blockDim.x + threadIdx.x;
    if (n >= N_NODES) return;
    float di = rsqrtf(d_dinv[n] + 1.0f);
    float xd = di * x[n];
    d_dinv[n] = di;
    d_xd[n] = xd;
    d_p[n] = xd;                    // self-loop seed (unnormalized)
}

// Pass 2: p'[d] += w * xd[s].  Single 4B gather per edge; grid-stride chunks.
__global__ void __launch_bounds__(TB)
k_p_edges(const int* __restrict__ src, const int* __restrict__ dst,
          const float* __restrict__ w) {
    const int stride = EDGE_GRID * TB;
    for (int c = blockIdx.x * TB + threadIdx.x; c < N_CHUNK4; c += stride) {
        int e = c * 4;
        int4   s4 = __ldcs((const int4*)  (src + e));
        int4   d4 = __ldcs((const int4*)  (dst + e));
        float4 w4 = __ldcs((const float4*)(w   + e));
        float x0 = __ldg(d_xd + s4.x), x1 = __ldg(d_xd + s4.y);
        float x2 = __ldg(d_xd + s4.z), x3 = __ldg(d_xd + s4.w);
        atomicAdd(&d_p[d4.x], w4.x * x0);
        atomicAdd(&d_p[d4.y], w4.y * x1);
        atomicAdd(&d_p[d4.z], w4.z * x2);
        atomicAdd(&d_p[d4.w], w4.w * x3);
    }
}

// Fused stats + gnode; SMALL grid (256 blocks) so the spin barrier has low
// contention, and the spin uses nanosleep backoff (poll rate cut ~100x).
//   Phase A: p = dinv*p', accumulate sum(p), sum(p^2) to d_sums, arrive.
//   Phase B: BN coefs from d_sums (b1 cancels); g = relu(a*q+beta)@W2;
//            gd = dinv*g; u seeded with gd (self term).
#define SG_NPT ((N_NODES + SG_GRID * TB - 1) / (SG_GRID * TB))   // nodes/thread (2)
__global__ void __launch_bounds__(TB)
k_statsgnode(const float* __restrict__ W1, const float* __restrict__ gamma,
             const float* __restrict__ beta, const float* __restrict__ W2) {
    int tid = threadIdx.x;
    int base = blockIdx.x * TB + tid;
    const int stride = SG_GRID * TB;

    // Phase A
    float pv[SG_NPT];
    float v = 0.0f, v2 = 0.0f;
    #pragma unroll
    for (int i = 0; i < SG_NPT; i++) {
        int n = base + i * stride;
        float t = 0.0f;
        if (n < N_NODES) t = d_dinv[n] * d_p[n];
        pv[i] = t;
        v += t; v2 += t * t;
    }
    #pragma unroll
    for (int off = 16; off > 0; off >>= 1) {
        v  += __shfl_down_sync(0xffffffffu, v,  off);
        v2 += __shfl_down_sync(0xffffffffu, v2, off);
    }
    __shared__ float s1[8], s2[8];
    int lane = tid & 31, warp = tid >> 5;
    if (lane == 0) { s1[warp] = v; s2[warp] = v2; }
    __syncthreads();
    if (warp == 0) {
        v  = (lane < 8) ? s1[lane] : 0.0f;
        v2 = (lane < 8) ? s2[lane] : 0.0f;
        #pragma unroll
        for (int off = 4; off > 0; off >>= 1) {
            v  += __shfl_down_sync(0xffffffffu, v,  off);
            v2 += __shfl_down_sync(0xffffffffu, v2, off);
        }
        if (lane == 0) { atomicAdd(&d_sums[0], v); atomicAdd(&d_sums[1], v2); }
    }
    // barrier with backoff
    __syncthreads();
    if (tid == 0) {
        __threadfence();
        atomicAdd(&d_bar_sg, 1u);
        while (*((volatile unsigned*)&d_bar_sg) < SG_GRID) __nanosleep(64);
    }
    __syncthreads();
    __threadfence();

    // Phase B
    float mp   = __ldcv(&d_sums[0]) * (1.0f / N_NODES);
    float sp2  = __ldcv(&d_sums[1]) * (1.0f / N_NODES);
    float varp = sp2 - mp * mp;
    __shared__ float sa[HIDDEN], sb[HIDDEN], sw[HIDDEN * EMB];
    if (tid < HIDDEN) {
        float wj = W1[tid];
        sa[tid] = wj * gamma[tid] * rsqrtf(wj * wj * varp + 1e-5f);
        sb[tid] = beta[tid];
    }
    if (tid < HIDDEN * EMB) sw[tid] = W2[tid];
    __syncthreads();
    #pragma unroll
    for (int i = 0; i < SG_NPT; i++) {
        int n = base + i * stride;
        if (n >= N_NODES) continue;
        float q = pv[i] - mp;
        float g0 = 0.0f, g1 = 0.0f;
        #pragma unroll
        for (int j = 0; j < HIDDEN; j++) {
            float r = fmaxf(sa[j] * q + sb[j], 0.0f);
            g0 = fmaf(r, sw[j * EMB + 0], g0);
            g1 = fmaf(r, sw[j * EMB + 1], g1);
        }
        float di = d_dinv[n];
        float2 gd = make_float2(di * g0, di * g1);
        d_gd[n] = gd;
        d_u[n] = gd;                // self-loop seed (unnormalized)
    }
}

// Pass 3: u[d] += w * gd[s].  One 8B gather + one f32x2 RED per edge.
__global__ void __launch_bounds__(TB)
k_l2_edges(const int* __restrict__ src, const int* __restrict__ dst,
           const float* __restrict__ w) {
    const int stride = EDGE_GRID * TB;
    for (int c = blockIdx.x * TB + threadIdx.x; c < N_CHUNK4; c += stride) {
        int e = c * 4;
        int4   s4 = __ldcs((const int4*)  (src + e));
        int4   d4 = __ldcs((const int4*)  (dst + e));
        float4 w4 = __ldcs((const float4*)(w   + e));
        float2 g0 = d_gd[s4.x], g1 = d_gd[s4.y], g2 = d_gd[s4.z], g3 = d_gd[s4.w];
        red_add_f32x2(&d_u[d4.x], w4.x * g0.x, w4.x * g0.y);
        red_add_f32x2(&d_u[d4.y], w4.y * g1.x, w4.y * g1.y);
        red_add_f32x2(&d_u[d4.z], w4.z * g2.x, w4.z * g2.y);
        red_add_f32x2(&d_u[d4.w], w4.w * g3.x, w4.w * g3.y);
    }
}

// Pool: t = dinv*u; smem pre-aggregation; last ticket block finalizes out and
// resets ALL persistent state for the next replay.
__global__ void k_pool(const int* __restrict__ batch, const float* __restrict__ b2,
                       float* __restrict__ out) {
    __shared__ float sacc[N_GRAPHS * EMB];
    __shared__ float scnt[N_GRAPHS];
    __shared__ bool  is_last;
    int tid = threadIdx.x;
    if (tid < N_GRAPHS * EMB) sacc[tid] = 0.0f;
    if (tid < N_GRAPHS) scnt[tid] = 0.0f;
    __syncthreads();
    int n = blockIdx.x * blockDim.x + tid;
    if (n < N_NODES) {
        int b = batch[n];
        float di = d_dinv[n];
        float2 u = d_u[n];
        atomicAdd(&sacc[b * EMB + 0], di * u.x);
        atomicAdd(&sacc[b * EMB + 1], di * u.y);
        atomicAdd(&scnt[b], 1.0f);
        d_dinv[n] = 0.0f;           // reset for next replay (after last use)
    }
    __syncthreads();
    if (tid < N_GRAPHS * EMB) atomicAdd(&d_acc[tid], sacc[tid]);
    if (tid < N_GRAPHS) atomicAdd(&d_cnt[tid], scnt[tid]);
    __threadfence();
    if (tid == 0) {
        unsigned old = atomicInc(&d_ticket, 0xffffffffu);
        is_last = (old == gridDim.x - 1);
    }
    __syncthreads();
    if (is_last) {
        if (tid < N_GRAPHS * EMB) {
            int g = tid / EMB, k = tid % EMB;
            float acc = __ldcv(&d_acc[tid]);
            float cnt = __ldcv(&d_cnt[g]);
            out[tid] = acc / fmaxf(cnt, 1.0f) + b2[k];
        }
        __syncthreads();
        // reset accumulators/counters for next replay
        if (tid < N_GRAPHS * EMB) d_acc[tid] = 0.0f;
        if (tid < N_GRAPHS) d_cnt[tid] = 0.0f;
        if (tid == 0) {
            d_sums[0] = 0.0f; d_sums[1] = 0.0f;
            d_bar_sg = 0u; d_ticket = 0u;
        }
    }
}

// ---------------- launch ----------------
extern "C" void kernel_launch(void* const* d_in, const int* in_sizes, int n_in,
                              void* d_out, int out_size) {
    const float* x     = (const float*)d_in[0];
    const int*   ei    = (const int*)  d_in[1];   // [2, E]: src row then dst row
    const float* ew    = (const float*)d_in[2];
    const int*   batch = (const int*)  d_in[3];
    const float* W1    = (const float*)d_in[4];
    // d_in[5] = b1 (cancels exactly inside batch-norm; unused)
    const float* gamma = (const float*)d_in[6];
    const float* beta  = (const float*)d_in[7];
    const float* W2    = (const float*)d_in[8];
    const float* b2    = (const float*)d_in[9];
    float* out = (float*)d_out;

    const int* src = ei;
    const int* dst = ei + N_EDGES;

    const int nodeBlocks = (N_NODES + TB - 1) / TB;

    k_deg       <<<EDGE_GRID, TB>>>(dst, ew);
    k_dinv      <<<nodeBlocks, TB>>>(x);
    k_p_edges   <<<EDGE_GRID, TB>>>(src, dst, ew);
    k_statsgnode<<<SG_GRID, TB>>>(W1, gamma, beta, W2);
    k_l2_edges  <<<EDGE_GRID, TB>>>(src, dst, ew);
    k_pool      <<<nodeBlocks, TB>>>(batch, b2, out);
}